// round 6
// baseline (speedup 1.0000x reference)
#include <cuda_runtime.h>
#include <cuda_bf16.h>

#define NPAIR 1024
#define NN 128
#define CC 64
#define NDIAG 255
#define DS2 130                      // bf16 smem row stride (halves)

#define INFV 1e30f
#define LOG2E 1.4426950408889634f
#define LN2f  0.6931471805599453f

#define STAGE_BYTES (2 * 32 * 132 * 4)   // 33792 B; Dsh bf16 128*130*2=33280 aliases it

// diag-major bf16 D: g_D[p*NDIAG*NN + d*NN + i], pre-scaled by log2(e)
__device__ __nv_bfloat16 g_D[(size_t)NPAIR * NDIAG * NN];
__device__ float g_bl[NPAIR];

__device__ __forceinline__ float ex2f(float x) {
    float r; asm("ex2.approx.ftz.f32 %0, %1;" : "=f"(r) : "f"(x)); return r;
}
__device__ __forceinline__ float lg2f(float x) {
    float r; asm("lg2.approx.ftz.f32 %0, %1;" : "=f"(r) : "f"(x)); return r;
}

// ---------------- Phase A: fp32 GEMM -> smem bf16 D -> coalesced diag-major store ---
__global__ void __launch_bounds__(256, 2) dtw_cost_kernel(const float* __restrict__ x,
                                                          const float* __restrict__ y) {
    extern __shared__ float sm[];            // staging; later aliased as Dsh (bf16)
    __shared__ float sx2[NN];
    __shared__ float sy2[NN];

    float* xs = sm;                          // [32][132]
    float* ys = sm + 32 * 132;               // [32][132]
    __nv_bfloat16* Dsh = (__nv_bfloat16*)sm; // [128][DS2]

    const int p   = blockIdx.x;
    const int tid = threadIdx.x;
    const float* __restrict__ xb = x + (size_t)p * NN * CC;
    const float* __restrict__ yb = y + (size_t)p * NN * CC;

    const int tm = tid >> 4;
    const int tn = tid & 15;
    const int i0 = tm * 8;
    const int j0 = tn * 8;

    float c[8][8];
#pragma unroll
    for (int m = 0; m < 8; m++)
#pragma unroll
        for (int n = 0; n < 8; n++) c[m][n] = 0.f;

    float accx = 0.f, accy = 0.f;

    for (int kc = 0; kc < 2; kc++) {
        __syncthreads();
        const int kbase = kc * 32;
        for (int t = tid; t < 128 * 32; t += 256) {
            int i  = t >> 5;
            int kk = t & 31;
            xs[kk * 132 + i] = xb[i * CC + kbase + kk];
            ys[kk * 132 + i] = yb[i * CC + kbase + kk];
        }
        __syncthreads();

        if (tid < 128) {
#pragma unroll 8
            for (int kk = 0; kk < 32; kk++) { float v = xs[kk * 132 + tid]; accx += v * v; }
        } else {
            int ii = tid - 128;
#pragma unroll 8
            for (int kk = 0; kk < 32; kk++) { float v = ys[kk * 132 + ii]; accy += v * v; }
        }

#pragma unroll 4
        for (int kk = 0; kk < 32; kk++) {
            float4 a0 = *(const float4*)&xs[kk * 132 + i0];
            float4 a1 = *(const float4*)&xs[kk * 132 + i0 + 4];
            float4 b0 = *(const float4*)&ys[kk * 132 + j0];
            float4 b1 = *(const float4*)&ys[kk * 132 + j0 + 4];
            float a[8] = {a0.x, a0.y, a0.z, a0.w, a1.x, a1.y, a1.z, a1.w};
            float b[8] = {b0.x, b0.y, b0.z, b0.w, b1.x, b1.y, b1.z, b1.w};
#pragma unroll
            for (int m = 0; m < 8; m++)
#pragma unroll
                for (int n = 0; n < 8; n++)
                    c[m][n] = fmaf(a[m], b[n], c[m][n]);
        }
    }

    __syncthreads();
    if (tid < 128) sx2[tid] = accx; else sy2[tid - 128] = accy;
    __syncthreads();                          // staging dead below

    // epilogue: bf16 D row-major into aliased smem (packed bf162 stores)
#pragma unroll
    for (int m = 0; m < 8; m++) {
        float xx = sx2[i0 + m];
        int rbase = (i0 + m) * DS2 + j0;
#pragma unroll
        for (int n = 0; n < 8; n += 2) {
            float v0 = (xx + sy2[j0 + n]     - 2.f * c[m][n])     * LOG2E;
            float v1 = (xx + sy2[j0 + n + 1] - 2.f * c[m][n + 1]) * LOG2E;
            __nv_bfloat162 h = __floats2bfloat162_rn(v0, v1);
            *(unsigned int*)&Dsh[rbase + n] = *(unsigned int*)&h;
        }
    }
    __syncthreads();

    // restage: coalesced diag-major u32 (bf16x2) global stores
    unsigned int* __restrict__ outD = (unsigned int*)(g_D + (size_t)p * NDIAG * NN);
    for (int t = tid; t < NDIAG * 64; t += 256) {
        int d  = t >> 6;
        int ip = t & 63;
        int i  = ip * 2;
        int ja = d - i;
        int jb = ja - 1;
        int jca = min(max(ja, 0), NN - 1);    // clamp: invalid cells masked in phase B
        int jcb = min(max(jb, 0), NN - 1);
        unsigned short a = *(unsigned short*)&Dsh[i * DS2 + jca];
        unsigned short b = *(unsigned short*)&Dsh[(i + 1) * DS2 + jcb];
        outD[(size_t)d * 64 + ip] = (unsigned int)a | ((unsigned int)b << 16);
    }
}

// ---------------- Phase B: warp-per-pair register-wavefront DP ----------------
__global__ void __launch_bounds__(32) dtw_dp_kernel() {
    const int p    = blockIdx.x;
    const int lane = threadIdx.x;
    const uint2* __restrict__ Dp = (const uint2*)(g_D + (size_t)p * NDIAG * NN);

    float r1[4], r2[4];
#pragma unroll
    for (int k = 0; k < 4; k++) { r1[k] = INFV; r2[k] = INFV; }

    uint2 pf[4];                              // depth-4 prefetch of diag D-lines
#pragma unroll
    for (int k = 0; k < 4; k++) pf[k] = Dp[k * 32 + lane];

    const int i_first = 4 * lane;

#pragma unroll 4
    for (int d = 0; d < NDIAG; d++) {
        uint2 u = pf[d & 3];
        if (d + 4 < NDIAG) pf[d & 3] = Dp[(d + 4) * 32 + lane];

        float2 f01 = __bfloat1622float2(*(__nv_bfloat162*)&u.x);  // cells k=0,1
        float2 f23 = __bfloat1622float2(*(__nv_bfloat162*)&u.y);  // cells k=2,3
        float dv[4] = {f01.x, f01.y, f23.x, f23.y};

        float upB = __shfl_up_sync(0xffffffffu, r1[3], 1);
        float dgB = __shfl_up_sync(0xffffffffu, r2[3], 1);
        if (lane == 0) { upB = INFV; dgB = (d == 0) ? 0.f : INFV; }

        float nw[4];
#pragma unroll
        for (int k = 0; k < 4; k++) {
            int i = i_first + k;
            int j = d - i;
            bool valid = (unsigned)j < (unsigned)NN;

            float up = (k == 0) ? upB : r1[k - 1];
            float dg = (k == 0) ? dgB : r2[k - 1];
            float lf = r1[k];

            float mn = fminf(lf, fminf(up, dg));
            float mx = fmaxf(lf, fmaxf(up, dg));
            float md = fmaxf(fminf(lf, up), fminf(fmaxf(lf, up), dg));
            float s  = 1.f + ex2f(mn - md) + ex2f(mn - mx);
            float r  = dv[k] + mn - lg2f(s);
            nw[k] = valid ? r : INFV;
        }
#pragma unroll
        for (int k = 0; k < 4; k++) { r2[k] = r1[k]; r1[k] = nw[k]; }
    }

    if (lane == 31) g_bl[p] = r1[3] * LN2f;   // R[127][127] in nat-log units
}

// ---------------- deterministic batch reduction ----------------
__global__ void dtw_reduce_kernel(float* __restrict__ out) {
    int b = threadIdx.x;
    if (b < 32) {
        float s = 0.f;
#pragma unroll
        for (int k = 0; k < 32; k++) s += g_bl[b * 32 + k];
        out[b] = s;
    }
}

extern "C" void kernel_launch(void* const* d_in, const int* in_sizes, int n_in,
                              void* d_out, int out_size) {
    (void)in_sizes; (void)n_in; (void)out_size;
    const float* x  = (const float*)d_in[0];
    const float* xr = (const float*)d_in[1];
    dtw_cost_kernel<<<NPAIR, 256, STAGE_BYTES>>>(x, xr);
    dtw_dp_kernel<<<NPAIR, 32>>>();
    dtw_reduce_kernel<<<1, 32>>>((float*)d_out);
}

// round 8
// speedup vs baseline: 1.3317x; 1.3317x over previous
#include <cuda_runtime.h>
#include <cuda_bf16.h>
#include <cstdint>

#define NPAIR 1024
#define NN 128
#define CC 64
#define NDIAG 255
#define DS2 130                      // bf16 Dsh row stride (halves)
#define SX 70                        // bf16 A/B smem row stride (halves): conflict-free frags

#define INFV 1e30f
#define LOG2E 1.4426950408889634f
#define LN2f  0.6931471805599453f

// dyn smem: A[128*70]bf16 (17920B) + B same => 35840B; Dsh 128*130*2=33280 aliases base
#define SMEM_BYTES (2 * NN * SX * 2)

// diag-major bf16 D: g_D[p*NDIAG*NN + d*NN + i], pre-scaled by log2(e)
__device__ __nv_bfloat16 g_D[(size_t)NPAIR * NDIAG * NN];
__device__ float g_bl[NPAIR];

__device__ __forceinline__ float ex2f(float x) {
    float r; asm("ex2.approx.ftz.f32 %0, %1;" : "=f"(r) : "f"(x)); return r;
}
__device__ __forceinline__ float lg2f(float x) {
    float r; asm("lg2.approx.ftz.f32 %0, %1;" : "=f"(r) : "f"(x)); return r;
}

__device__ __forceinline__ void mma_bf16(float c[4], uint32_t a0, uint32_t a1, uint32_t a2,
                                         uint32_t a3, uint32_t b0, uint32_t b1) {
    asm volatile(
        "mma.sync.aligned.m16n8k16.row.col.f32.bf16.bf16.f32 "
        "{%0,%1,%2,%3}, {%4,%5,%6,%7}, {%8,%9}, {%0,%1,%2,%3};"
        : "+f"(c[0]), "+f"(c[1]), "+f"(c[2]), "+f"(c[3])
        : "r"(a0), "r"(a1), "r"(a2), "r"(a3), "r"(b0), "r"(b1));
}

// ---------------- Phase A: HMMA bf16 GEMM -> bf16 Dsh -> diag-major store ------------
__global__ void __launch_bounds__(256, 2) dtw_cost_kernel(const float* __restrict__ x,
                                                          const float* __restrict__ y) {
    extern __shared__ __nv_bfloat16 smh[];        // xs[128][SX], ys[128][SX]
    __shared__ float sx2[NN];
    __shared__ float sy2[NN];

    __nv_bfloat16* xs = smh;
    __nv_bfloat16* ys = smh + NN * SX;
    __nv_bfloat16* Dsh = smh;                     // aliased after GEMM reads done

    const int p    = blockIdx.x;
    const int tid  = threadIdx.x;
    const int wid  = tid >> 5;
    const int lane = tid & 31;
    const int m0   = wid * 16;

    const float* __restrict__ xb = x + (size_t)p * NN * CC;
    const float* __restrict__ yb = y + (size_t)p * NN * CC;

    // load fp32 -> bf16 smem; fused row sum-of-squares (warp reduce over 32 lanes)
    for (int r = m0; r < m0 + 16; r++) {
        float2 vx = *(const float2*)&xb[r * CC + lane * 2];
        float2 vy = *(const float2*)&yb[r * CC + lane * 2];
        __nv_bfloat162 hx = __floats2bfloat162_rn(vx.x, vx.y);
        __nv_bfloat162 hy = __floats2bfloat162_rn(vy.x, vy.y);
        *(uint32_t*)&xs[r * SX + lane * 2] = *(uint32_t*)&hx;
        *(uint32_t*)&ys[r * SX + lane * 2] = *(uint32_t*)&hy;
        float sxq = vx.x * vx.x + vx.y * vx.y;
        float syq = vy.x * vy.x + vy.y * vy.y;
#pragma unroll
        for (int o = 16; o > 0; o >>= 1) {
            sxq += __shfl_xor_sync(0xffffffffu, sxq, o);
            syq += __shfl_xor_sync(0xffffffffu, syq, o);
        }
        if (lane == 0) { sx2[r] = sxq; sy2[r] = syq; }
    }
    __syncthreads();

    // fragment indices
    const int frow = lane >> 2;          // 0..7
    const int fk   = (lane & 3) * 2;     // 0,2,4,6

    // preload A fragments for all 4 k-steps
    uint32_t a[4][4];
#pragma unroll
    for (int k = 0; k < 4; k++) {
        int kb = k * 16 + fk;
        a[k][0] = *(uint32_t*)&xs[(m0 + frow)     * SX + kb];
        a[k][1] = *(uint32_t*)&xs[(m0 + frow + 8) * SX + kb];
        a[k][2] = *(uint32_t*)&xs[(m0 + frow)     * SX + kb + 8];
        a[k][3] = *(uint32_t*)&xs[(m0 + frow + 8) * SX + kb + 8];
    }

    float acc[16][4];
#pragma unroll
    for (int nt = 0; nt < 16; nt++) {
        acc[nt][0] = acc[nt][1] = acc[nt][2] = acc[nt][3] = 0.f;
        const int nrow = nt * 8 + frow;
#pragma unroll
        for (int k = 0; k < 4; k++) {
            int kb = k * 16 + fk;
            uint32_t b0 = *(uint32_t*)&ys[nrow * SX + kb];
            uint32_t b1 = *(uint32_t*)&ys[nrow * SX + kb + 8];
            mma_bf16(acc[nt], a[k][0], a[k][1], a[k][2], a[k][3], b0, b1);
        }
    }
    __syncthreads();                     // all GEMM smem reads done; alias as Dsh

    // epilogue: C frags -> D bf16 row-major in smem
    const int ccol = (lane & 3) * 2;
#pragma unroll
    for (int nt = 0; nt < 16; nt++) {
        int n0 = nt * 8 + ccol;
        int r0 = m0 + frow;
        float xx0 = sx2[r0], xx1 = sx2[r0 + 8];
        float yy0 = sy2[n0], yy1 = sy2[n0 + 1];
        float d00 = (xx0 + yy0 - 2.f * acc[nt][0]) * LOG2E;
        float d01 = (xx0 + yy1 - 2.f * acc[nt][1]) * LOG2E;
        float d10 = (xx1 + yy0 - 2.f * acc[nt][2]) * LOG2E;
        float d11 = (xx1 + yy1 - 2.f * acc[nt][3]) * LOG2E;
        __nv_bfloat162 h0 = __floats2bfloat162_rn(d00, d01);
        __nv_bfloat162 h1 = __floats2bfloat162_rn(d10, d11);
        *(uint32_t*)&Dsh[r0 * DS2 + n0]       = *(uint32_t*)&h0;
        *(uint32_t*)&Dsh[(r0 + 8) * DS2 + n0] = *(uint32_t*)&h1;
    }
    __syncthreads();

    // restage: coalesced diag-major u32 (bf16x2) global stores
    unsigned int* __restrict__ outD = (unsigned int*)(g_D + (size_t)p * NDIAG * NN);
    for (int t = tid; t < NDIAG * 64; t += 256) {
        int d  = t >> 6;
        int ip = t & 63;
        int ii = ip * 2;
        int ja = d - ii;
        int jb = ja - 1;
        int jca = min(max(ja, 0), NN - 1);
        int jcb = min(max(jb, 0), NN - 1);
        unsigned short va = *(unsigned short*)&Dsh[ii * DS2 + jca];
        unsigned short vb = *(unsigned short*)&Dsh[(ii + 1) * DS2 + jcb];
        outD[(size_t)d * 64 + ip] = (unsigned int)va | ((unsigned int)vb << 16);
    }
}

// ---------------- Phase B: warp-per-pair register-wavefront DP (1 shfl/diag) ---------
__global__ void __launch_bounds__(32) dtw_dp_kernel() {
    const int p    = blockIdx.x;
    const int lane = threadIdx.x;
    const uint2* __restrict__ Dp = (const uint2*)(g_D + (size_t)p * NDIAG * NN);

    float r1[4], r2[4];
#pragma unroll
    for (int k = 0; k < 4; k++) { r1[k] = INFV; r2[k] = INFV; }

    uint2 pf[4];
#pragma unroll
    for (int k = 0; k < 4; k++) pf[k] = Dp[k * 32 + lane];

    const int i_first = 4 * lane;
    float upB = INFV;                                // r1[3] of lane-1
    float dgB = (lane == 0) ? 0.f : INFV;            // r2[3] of lane-1 (corner at d=0)

#pragma unroll 4
    for (int d = 0; d < NDIAG; d++) {
        uint2 u = pf[d & 3];
        if (d + 4 < NDIAG) pf[d & 3] = Dp[(d + 4) * 32 + lane];

        float2 f01 = __bfloat1622float2(*(__nv_bfloat162*)&u.x);
        float2 f23 = __bfloat1622float2(*(__nv_bfloat162*)&u.y);
        float dv[4] = {f01.x, f01.y, f23.x, f23.y};

        float nw[4];
#pragma unroll
        for (int k = 0; k < 4; k++) {
            int i = i_first + k;
            int j = d - i;
            bool valid = (unsigned)j < (unsigned)NN;

            float up = (k == 0) ? upB : r1[k - 1];
            float dg = (k == 0) ? dgB : r2[k - 1];
            float lf = r1[k];

            float mn = fminf(lf, fminf(up, dg));
            float mx = fmaxf(lf, fmaxf(up, dg));
            float md = fmaxf(fminf(lf, up), fminf(fmaxf(lf, up), dg));
            float s  = 1.f + ex2f(mn - md) + ex2f(mn - mx);
            float r  = dv[k] + mn - lg2f(s);
            nw[k] = valid ? r : INFV;
        }

        // dgB(d+1) == upB(d); only one shfl needed per diagonal
        float newUp = __shfl_up_sync(0xffffffffu, nw[3], 1);
        dgB = upB;
        upB = (lane == 0) ? INFV : newUp;

#pragma unroll
        for (int k = 0; k < 4; k++) { r2[k] = r1[k]; r1[k] = nw[k]; }
    }

    if (lane == 31) g_bl[p] = r1[3] * LN2f;
}

// ---------------- deterministic batch reduction ----------------
__global__ void dtw_reduce_kernel(float* __restrict__ out) {
    int b = threadIdx.x;
    if (b < 32) {
        float s = 0.f;
#pragma unroll
        for (int k = 0; k < 32; k++) s += g_bl[b * 32 + k];
        out[b] = s;
    }
}

extern "C" void kernel_launch(void* const* d_in, const int* in_sizes, int n_in,
                              void* d_out, int out_size) {
    (void)in_sizes; (void)n_in; (void)out_size;
    const float* x  = (const float*)d_in[0];
    const float* xr = (const float*)d_in[1];
    cudaFuncSetAttribute(dtw_cost_kernel, cudaFuncAttributeMaxDynamicSharedMemorySize, SMEM_BYTES);
    dtw_cost_kernel<<<NPAIR, 256, SMEM_BYTES>>>(x, xr);
    dtw_dp_kernel<<<NPAIR, 32>>>();
    dtw_reduce_kernel<<<1, 32>>>((float*)d_out);
}